// round 16
// baseline (speedup 1.0000x reference)
#include <cuda_runtime.h>
#include <cuda_fp16.h>
#include <math.h>

#define Bsz  256
#define Tlen 64
#define Hdim 1024
#define Xdim 512
#define Edim 256
#define DIN  768
#define G4   4096
#define NTAG 512

// ---- scratch layout ----
// floats:
//   xpart   @0          (1,048,576)
//   embproj @1,048,576  (2,097,152)
//   logits  @3,407,872  (8,388,608)
//   rownll  @11,796,480 (16,384)
//   rowmask @11,812,864 (16,384)
// fp16 region at float offset 11,829,248 (half-element offsets):
//   whh 0 (4,194,304)   wout 8,388,608 (524,288)
//   hA 9,437,184  hB 9,699,328
//   hs 9,961,472 (16,777,216)
__device__ float g_scratch[33849344];
__device__ int   g_mask_mode;
__device__ unsigned g_bar_arrive;
__device__ unsigned g_bar_gen;
__device__ unsigned g_arr2[2];
__device__ unsigned g_gen2[2];
__device__ int      g_use_tc;

// ---------------------------------------------------------------------------
// PTX helpers (portable)
// ---------------------------------------------------------------------------
#define MMA4F(c, a, b0_, b1_) \
    asm volatile("mma.sync.aligned.m16n8k16.row.col.f32.f16.f16.f32 " \
                 "{%0,%1,%2,%3},{%4,%5,%6,%7},{%8,%9},{%0,%1,%2,%3};" \
                 : "+f"((c)[0]), "+f"((c)[1]), "+f"((c)[2]), "+f"((c)[3]) \
                 : "r"((a)[0]), "r"((a)[1]), "r"((a)[2]), "r"((a)[3]), \
                   "r"(b0_), "r"(b1_))

#define LDSM4(r, addr) \
    asm volatile("ldmatrix.sync.aligned.m8n8.x4.shared.b16 {%0,%1,%2,%3}, [%4];" \
                 : "=r"((r)[0]), "=r"((r)[1]), "=r"((r)[2]), "=r"((r)[3]) \
                 : "r"(addr))

#define CP16(dst, src) \
    asm volatile("cp.async.cg.shared.global [%0], [%1], 16;" :: "r"(dst), "l"(src))
#define CPCOMMIT() asm volatile("cp.async.commit_group;" ::: "memory")
#define CPWAIT(n)  asm volatile("cp.async.wait_group %0;" :: "n"(n) : "memory")
#define CP_ARRIVE(mb) \
    asm volatile("cp.async.mbarrier.arrive.noinc.shared.b64 [%0];" :: "r"(mb) : "memory")

#define FFMA2(d, a, b) asm("fma.rn.f32x2 %0, %1, %2, %0;" : "+l"(d) : "l"(a), "l"(b))
union F2U { unsigned long long u; float2 f; };
__device__ __forceinline__ unsigned long long dup2(float a) {
    unsigned x = __float_as_uint(a);
    return ((unsigned long long)x << 32) | (unsigned long long)x;
}

__device__ __forceinline__ unsigned smem_u32(const void* p) {
    return (unsigned)__cvta_generic_to_shared(p);
}

// fast activations (safe at +/-inf)
__device__ __forceinline__ float fsig(float x) {
    return __fdividef(1.f, 1.f + __expf(-x));
}
__device__ __forceinline__ float ftanh(float x) {
    return 1.f - __fdividef(2.f, __expf(2.f * x) + 1.f);
}

// ---------------------------------------------------------------------------
// tcgen05 helpers — ONLY compiled on the sm_100a pass.
// ---------------------------------------------------------------------------
#if defined(__CUDA_ARCH_FEAT_SM100_ALL)
__device__ __forceinline__ bool elect1() {
    unsigned p;
    asm volatile("{\n\t.reg .pred p;\n\telect.sync _|p, 0xFFFFFFFF;\n\tselp.b32 %0,1,0,p;\n\t}"
                 : "=r"(p));
    return p != 0;
}
__device__ __forceinline__ unsigned long long mk_desc(unsigned addr) {
    // SW128, version=1 (Blackwell), SBO=64, LBO=1 (K-major, 128B rows)
    return 0x4000404000010000ULL | ((unsigned long long)(addr >> 4) & 0x3FFF);
}
__device__ __forceinline__ void tc_mma_f16_ss(unsigned d, unsigned long long ad,
                                              unsigned long long bd, unsigned idesc,
                                              unsigned en)
{
    asm volatile(
        "{\n\t.reg .pred p;\n\tsetp.ne.u32 p, %5, 0;\n\t"
        "tcgen05.mma.cta_group::1.kind::f16 [%0], %1, %2, %3, {%4, %4, %4, %4}, p;\n\t}"
        :: "r"(d), "l"(ad), "l"(bd), "r"(idesc), "r"(0u), "r"(en)
        : "memory");
}
#define TC_ALLOC(smaddr, n) \
    asm volatile("tcgen05.alloc.cta_group::1.sync.aligned.shared::cta.b32 [%0], %1;" \
                 :: "r"(smaddr), "r"((unsigned)(n)) : "memory")
#define TC_DEALLOC(base, n) \
    asm volatile("tcgen05.dealloc.cta_group::1.sync.aligned.b32 %0, %1;" \
                 :: "r"(base), "r"((unsigned)(n)))
#define TC_COMMIT(mb) \
    asm volatile("tcgen05.commit.cta_group::1.mbarrier::arrive::one.shared::cluster.b64 [%0];" \
                 :: "r"(mb) : "memory")
#define TC_FENCE_AFTER()  asm volatile("tcgen05.fence::after_thread_sync;" ::: "memory")
#define TC_FENCE_BEFORE() asm volatile("tcgen05.fence::before_thread_sync;" ::: "memory")
#define TC_WAIT_LD()      asm volatile("tcgen05.wait::ld.sync.aligned;" ::: "memory")

#define MBAR_INIT(mb, cnt) \
    asm volatile("mbarrier.init.shared.b64 [%0], %1;" :: "r"(mb), "r"((unsigned)(cnt)) : "memory")
#define MBAR_WAIT(mb, par) do { \
    unsigned _m = (mb), _p = (par), _d; \
    asm volatile("{\n\t.reg .pred p;\n\t" \
                 "mbarrier.try_wait.parity.acquire.cta.shared::cta.b64 p, [%1], %2;\n\t" \
                 "selp.b32 %0,1,0,p;\n\t}" : "=r"(_d) : "r"(_m), "r"(_p) : "memory"); \
    if (!_d) { \
        asm volatile("{\n\t.reg .pred P1;\n\t" \
                     "WL%=:\n\t" \
                     "mbarrier.try_wait.parity.acquire.cta.shared::cta.b64 P1, [%0], %1, 0x989680;\n\t" \
                     "@P1 bra.uni WD%=;\n\tbra.uni WL%=;\n\tWD%=:\n\t}" \
                     :: "r"(_m), "r"(_p) : "memory"); \
    } \
} while(0)

#define TC_LD32(r, addr) \
    asm volatile("tcgen05.ld.sync.aligned.32x32b.x32.b32 " \
        "{%0,%1,%2,%3,%4,%5,%6,%7,%8,%9,%10,%11,%12,%13,%14,%15," \
        "%16,%17,%18,%19,%20,%21,%22,%23,%24,%25,%26,%27,%28,%29,%30,%31}, [%32];" \
        : "=r"((r)[0]),"=r"((r)[1]),"=r"((r)[2]),"=r"((r)[3]), \
          "=r"((r)[4]),"=r"((r)[5]),"=r"((r)[6]),"=r"((r)[7]), \
          "=r"((r)[8]),"=r"((r)[9]),"=r"((r)[10]),"=r"((r)[11]), \
          "=r"((r)[12]),"=r"((r)[13]),"=r"((r)[14]),"=r"((r)[15]), \
          "=r"((r)[16]),"=r"((r)[17]),"=r"((r)[18]),"=r"((r)[19]), \
          "=r"((r)[20]),"=r"((r)[21]),"=r"((r)[22]),"=r"((r)[23]), \
          "=r"((r)[24]),"=r"((r)[25]),"=r"((r)[26]),"=r"((r)[27]), \
          "=r"((r)[28]),"=r"((r)[29]),"=r"((r)[30]),"=r"((r)[31]) \
        : "r"(addr))

// idesc: f32 accum, f16 a/b, M=128, N=64
#define IDESC_F16 0x08100010u
#endif // __CUDA_ARCH_FEAT_SM100_ALL

// ---------------------------------------------------------------------------
// Conversion kernels (single fp16)
// ---------------------------------------------------------------------------
__global__ void interleave_whh(const float* __restrict__ W, __half* __restrict__ out)
{
    int c = blockIdx.x;                 // gate-interleaved row c = j*4 + g
    int j = c >> 2, g = c & 3;
    const float* src = W + (size_t)(g * Hdim + j) * Hdim;
    int k = threadIdx.x * 4;
    float4 v = *(const float4*)&src[k];
    size_t o = (size_t)c * Hdim + k;
    out[o + 0] = __float2half_rn(v.x);
    out[o + 1] = __float2half_rn(v.y);
    out[o + 2] = __float2half_rn(v.z);
    out[o + 3] = __float2half_rn(v.w);
}

__global__ void conv16(const float* __restrict__ src, __half* __restrict__ dst)
{
    int i = (blockIdx.x * 256 + threadIdx.x) * 4;
    float4 v = *(const float4*)&src[i];
    dst[i + 0] = __float2half_rn(v.x);
    dst[i + 1] = __float2half_rn(v.y);
    dst[i + 2] = __float2half_rn(v.z);
    dst[i + 3] = __float2half_rn(v.w);
}

// ---------------------------------------------------------------------------
// Merged projection GEMM (f32x2): one launch computes
//   by<2 : xpart[m0..m0+127]   = x @ W_ih[:, :512]^T + b_ih + b_hh
//   by>=2: embproj[m0..m0+127] = emb @ W_ih[:, 512:768]^T
// Grid (64, 6), 256 threads.
// ---------------------------------------------------------------------------
__global__ __launch_bounds__(256) void proj_dual(
    const float* __restrict__ x,
    const float* __restrict__ emb,
    const float* __restrict__ W_ih,
    float* __restrict__ xpart,
    float* __restrict__ embproj,
    const float* __restrict__ b_ih,
    const float* __restrict__ b_hh)
{
    const int by = blockIdx.y;
    const float* A; const float* Bm; float* C;
    const float *bias0, *bias1;
    int lda, K, m0;
    if (by < 2) {
        A = x;  lda = Xdim; K = Xdim; m0 = by * 128;
        Bm = W_ih; C = xpart; bias0 = b_ih; bias1 = b_hh;
    } else {
        A = emb; lda = Edim; K = Edim; m0 = (by - 2) * 128;
        Bm = W_ih + Xdim; C = embproj; bias0 = nullptr; bias1 = nullptr;
    }
    const int ldb = DIN, ldc = G4;

    __shared__ unsigned long long As2[16][128];
    __shared__ float Bs[16][64];
    const int n0 = blockIdx.x * 64;
    const int tid = threadIdx.x;
    const int rg = tid >> 4;
    const int cg = tid & 15;
    unsigned long long acc[8][2];
    #pragma unroll
    for (int i = 0; i < 8; i++) { acc[i][0] = 0ull; acc[i][1] = 0ull; }
    const int fm = tid >> 2;
    const int fk = (tid & 3) * 4;

    for (int k0 = 0; k0 < K; k0 += 16) {
        __syncthreads();
        #pragma unroll
        for (int half = 0; half < 2; half++) {
            int m = fm + half * 64;
            float4 v = *(const float4*)&A[(size_t)(m0 + m) * lda + k0 + fk];
            As2[fk + 0][m] = dup2(v.x);
            As2[fk + 1][m] = dup2(v.y);
            As2[fk + 2][m] = dup2(v.z);
            As2[fk + 3][m] = dup2(v.w);
        }
        {
            float4 v = *(const float4*)&Bm[(size_t)(n0 + fm) * ldb + k0 + fk];
            Bs[fk + 0][fm] = v.x; Bs[fk + 1][fm] = v.y;
            Bs[fk + 2][fm] = v.z; Bs[fk + 3][fm] = v.w;
        }
        __syncthreads();
        #pragma unroll
        for (int k = 0; k < 16; k++) {
            const ulonglong2* ap = (const ulonglong2*)&As2[k][rg * 8];
            ulonglong2 bv = *(const ulonglong2*)&Bs[k][cg * 4];
            #pragma unroll
            for (int i2 = 0; i2 < 4; i2++) {
                ulonglong2 a = ap[i2];
                FFMA2(acc[2 * i2 + 0][0], a.x, bv.x);
                FFMA2(acc[2 * i2 + 0][1], a.x, bv.y);
                FFMA2(acc[2 * i2 + 1][0], a.y, bv.x);
                FFMA2(acc[2 * i2 + 1][1], a.y, bv.y);
            }
        }
    }
    #pragma unroll
    for (int i = 0; i < 8; i++) {
        int m = m0 + rg * 8 + i;
        #pragma unroll
        for (int p = 0; p < 2; p++) {
            int n = n0 + cg * 4 + p * 2;
            F2U u; u.u = acc[i][p];
            float v0 = u.f.x, v1 = u.f.y;
            if (bias0) { v0 += bias0[n]; v1 += bias0[n + 1]; }
            if (bias1) { v0 += bias1[n]; v1 += bias1[n + 1]; }
            *(float2*)&C[(size_t)m * ldc + n] = make_float2(v0, v1);
        }
    }
}

// ---------------------------------------------------------------------------
// mma.sync fallback mainloop: single-term fp16. 64m x 128n.
// 3 stages x 15360 B: A[64][40]@0, B[128][40]@5120.
// ---------------------------------------------------------------------------
__device__ __forceinline__ void mma_mainloop1(
    const __half* __restrict__ gA, const __half* __restrict__ gB,
    unsigned smem_u, int tid, float acc[2][4][4])
{
    const int lane = tid & 31, w = tid >> 5;
    const int wm = w & 1, wn = w >> 1;
    const int lrow = (lane & 7) + ((lane >> 3) & 1) * 8;
    const int lcol = (lane >> 4) * 8;
    const unsigned aoff = ((wm * 32 + lrow) * 40 + lcol) * 2;
    const unsigned boff = ((wn * 32 + lrow) * 40 + lcol) * 2;

    const int ar = tid >> 2;
    const int br = tid >> 1;
    const unsigned dA  = (ar * 40 + (tid & 3) * 8) * 2;
    const unsigned dB0 = (br * 40 + (tid & 1) * 16) * 2;
    const unsigned dB1 = dB0 + 16;

    #pragma unroll
    for (int s = 0; s < 2; s++) {
        unsigned sb = smem_u + s * 15360;
        int k0 = s * 32;
        CP16(sb + dA,         gA + k0);
        CP16(sb + 5120 + dB0, gB + k0);
        CP16(sb + 5120 + dB1, gB + k0 + 8);
        CPCOMMIT();
    }

    for (int i = 0; i < 32; i++) {
        if (i < 31) { CPWAIT(1); } else { CPWAIT(0); }
        __syncthreads();
        if (i + 2 < 32) {
            unsigned sb = smem_u + ((i + 2) % 3) * 15360;
            int k0 = (i + 2) * 32;
            CP16(sb + dA,         gA + k0);
            CP16(sb + 5120 + dB0, gB + k0);
            CP16(sb + 5120 + dB1, gB + k0 + 8);
            CPCOMMIT();
        }
        unsigned sb = smem_u + (i % 3) * 15360;
        #pragma unroll
        for (int kh = 0; kh < 2; kh++) {
            const unsigned kb = kh * 32;
            unsigned a0[4], a1[4];
            LDSM4(a0, sb + aoff + kb);
            LDSM4(a1, sb + aoff + 1280 + kb);
            unsigned bh0[4], bh1[4];
            LDSM4(bh0, sb + 5120 + boff + kb);
            LDSM4(bh1, sb + 5120 + boff + 1280 + kb);
            #pragma unroll
            for (int nt = 0; nt < 4; nt++) {
                const unsigned* bhp = (nt < 2) ? bh0 : bh1;
                unsigned h0v = bhp[nt & 1], h1v = bhp[(nt & 1) + 2];
                MMA4F(acc[0][nt], a0, h0v, h1v);
                MMA4F(acc[1][nt], a1, h0v, h1v);
            }
        }
    }
}

// ---------------------------------------------------------------------------
// Barriers
// ---------------------------------------------------------------------------
__global__ void init_bar() {
    g_bar_arrive = 0; g_bar_gen = 0;
    g_arr2[0] = 0; g_arr2[1] = 0;
    g_gen2[0] = 0; g_gen2[1] = 0;
#if defined(__CUDA_ARCH_FEAT_SM100_ALL)
    g_use_tc = 1;
#else
    g_use_tc = 0;
#endif
}

__device__ __forceinline__ void grid_sync(int tid, unsigned gen)
{
    __syncthreads();
    if (tid == 0) {
        __threadfence();
        unsigned a = atomicAdd(&g_bar_arrive, 1);
        if (a == 127) {
            g_bar_arrive = 0;
            __threadfence();
            atomicExch(&g_bar_gen, gen);
        } else {
            while (atomicAdd(&g_bar_gen, 0u) < gen) __nanosleep(64);
            __threadfence();
        }
    }
    __syncthreads();
}

// lstm tcgen05 stage: A0 16K @0, A1 @16384, B0 8K @32768, B1 @40960
#define LSTG 49152
#define LNS  4
#define DSMEM_LSTM (LNS * LSTG)   // 196608
// logits tcgen05 stage
#define STG_SZ 24576
#define N_STG  8

// ---------------------------------------------------------------------------
// Persistent LSTM sequence kernel — dual path.
// tcgen05: block = 128 batch x 64 gate-cols (16 j x 4 gates, rows j*4+g),
// K-chunk = 128 (2 sub-tiles), 4-stage pipeline.
// Producer/consumer decoupled: full[s] (count 256, cp.async.mbarrier.arrive
// .noinc per thread) gates the single MMA-issuer; done[s] (tcgen05.commit)
// gates stage reuse by all producers. No __syncthreads / CPWAIT in the loop.
// Lap-safety: round-2 arrivals on full[s] require every thread to have passed
// its done[s] round-1 wait; round-2 done commits require round-2 full = all
// threads — no two-phase lap on either barrier.
// ---------------------------------------------------------------------------
__global__ __launch_bounds__(256, 1) void lstm_seq(
    __half* hA, __half* hB,
    const float* __restrict__ c0,
    const float* __restrict__ xpart,
    const float* __restrict__ embproj,
    __half* __restrict__ hs,
    const __half* __restrict__ whh,
    const int* __restrict__ atom_truth)
{
#if defined(__CUDA_ARCH_FEAT_SM100_ALL)
    extern __shared__ __align__(1024) unsigned char dsm[];
    __shared__ unsigned s_tmem;
    __shared__ __align__(8) unsigned long long s_full[LNS];
    __shared__ __align__(8) unsigned long long s_done[LNS];

    const unsigned smem_u = smem_u32(dsm);
    const int tid = threadIdx.x;
    const int wid = tid >> 5, lane = tid & 31;
    const int bx = blockIdx.x;
    const int half = bx >> 6;
    const int b0 = half * 128;
    const int ntb = bx & 63;
    const int c0g = ntb * 64;
    const int jb = ntb * 16;

    if (tid == 0) {
        #pragma unroll
        for (int i = 0; i < LNS; i++) {
            MBAR_INIT(smem_u32(&s_full[i]), 256);
            MBAR_INIT(smem_u32(&s_done[i]), 1);
        }
    }
    __syncthreads();
    if (wid == 0) TC_ALLOC(smem_u32(&s_tmem), 512);
    __syncthreads();
    const unsigned tmem = s_tmem;
    unsigned fullu[LNS], doneu[LNS];
    #pragma unroll
    for (int i = 0; i < LNS; i++) {
        fullu[i] = smem_u32(&s_full[i]);
        doneu[i] = smem_u32(&s_done[i]);
    }
    int mfp[LNS] = {0, 0, 0, 0};   // full-phase (MMA issuer only)
    int dph[LNS] = {0, 0, 0, 0};   // done-phase (all threads)

    // fill geometry
    const int ra = tid >> 1, ca = (tid & 1) * 4;       // A: row, 4 x 16B per sub
    const int rb = tid >> 2, cb2 = (tid & 3) * 2;      // B: row, 2 x 16B per sub
    const int ram = ra & 7, rbm = rb & 7;
    const __half* Bsrc = whh + (size_t)(c0g + rb) * Hdim;
    const __half* Asrc;   // set per step

    // epilogue geometry
    const int b = b0 + (wid & 3) * 32 + lane;
    const int jh = (wid >> 2) * 8;
    float creg[8];
    {
        const float* cp = c0 + (size_t)b * Hdim + jb + jh;
        float4 v0 = *(const float4*)&cp[0];
        float4 v1 = *(const float4*)&cp[4];
        creg[0] = v0.x; creg[1] = v0.y; creg[2] = v0.z; creg[3] = v0.w;
        creg[4] = v1.x; creg[5] = v1.y; creg[6] = v1.z; creg[7] = v1.w;
    }

    // k-chunk = 128 elements; stage holds 2 sub-tiles of 64
    #define FILL_B(kc_, st_) do { \
        unsigned ab = smem_u + (st_) * LSTG + 32768; \
        const __half* bs = Bsrc + (kc_) * 128; \
        _Pragma("unroll") \
        for (int sub = 0; sub < 2; sub++) { \
            _Pragma("unroll") \
            for (int c = 0; c < 2; c++) { \
                int cc = cb2 + c; \
                unsigned d = rb * 128 + ((cc ^ rbm) * 16); \
                CP16(ab + sub * 8192 + d, bs + sub * 64 + cc * 8); \
            } \
        } \
    } while (0)

    #define FILL_A(kc_, st_) do { \
        unsigned ab = smem_u + (st_) * LSTG; \
        const __half* sh = Asrc + (kc_) * 128; \
        _Pragma("unroll") \
        for (int sub = 0; sub < 2; sub++) { \
            _Pragma("unroll") \
            for (int c = 0; c < 4; c++) { \
                int cc = ca + c; \
                unsigned d = ra * 128 + ((cc ^ ram) * 16); \
                CP16(ab + sub * 16384 + d, sh + sub * 64 + cc * 8); \
            } \
        } \
    } while (0)

    // W prefetch for step 0: chunks 0..2 into stages 0..2 (arrive deferred
    // to the matching A fill — noinc arrival covers all prior cp.asyncs)
    FILL_B(0, 0); FILL_B(1, 1); FILL_B(2, 2);

    for (int t = 0; t < Tlen; t++) {
        const __half* hin = (t & 1) ? hB : hA;
        __half* hout      = (t & 1) ? hA : hB;
        Asrc = hin + (size_t)(b0 + ra) * Hdim;

        FILL_A(0, 0); CP_ARRIVE(fullu[0]);
        FILL_A(1, 1); CP_ARRIVE(fullu[1]);
        FILL_A(2, 2); CP_ARRIVE(fullu[2]);

        for (int kc = 0; kc < 8; kc++) {
            if (wid == 0 && elect1()) {
                int s = kc & 3;
                MBAR_WAIT(fullu[s], (unsigned)(mfp[s] & 1));
                mfp[s]++;
                unsigned sb = smem_u + s * LSTG;
                #pragma unroll
                for (int sub = 0; sub < 2; sub++) {
                    unsigned long long ad = mk_desc(sb + sub * 16384);
                    unsigned long long bd = mk_desc(sb + 32768 + sub * 8192);
                    #pragma unroll
                    for (int ks = 0; ks < 4; ks++) {
                        unsigned en0 = (kc == 0 && sub == 0 && ks == 0) ? 0u : 1u;
                        tc_mma_f16_ss(tmem, ad + ks * 2, bd + ks * 2, IDESC_F16, en0);
                    }
                }
                TC_COMMIT(doneu[s]);
            }
            if (kc + 3 < 8) {
                if (kc >= 1) {
                    int s = (kc - 1) & 3;
                    MBAR_WAIT(doneu[s], (unsigned)(dph[s] & 1));
                    dph[s]++;
                }
                int st = (kc + 3) & 3;
                FILL_A(kc + 3, st);
                FILL_B(kc + 3, st);
                CP_ARRIVE(fullu[st]);
            }
        }

        // prefetch epilogue operands while tail MMAs drain
        int tok = (t == 0) ? 0 : atom_truth[b * Tlen + (t - 1)];
        const float* xp = xpart + (size_t)b * G4 + jb + jh;
        const float* ep = embproj + (size_t)tok * G4 + jb + jh;
        float xg[4][8], eg[4][8];
        #pragma unroll
        for (int p = 0; p < 4; p++) {
            float4 a0 = *(const float4*)&xp[p * Hdim];
            float4 a1 = *(const float4*)&xp[p * Hdim + 4];
            float4 e0 = *(const float4*)&ep[p * Hdim];
            float4 e1 = *(const float4*)&ep[p * Hdim + 4];
            xg[p][0] = a0.x; xg[p][1] = a0.y; xg[p][2] = a0.z; xg[p][3] = a0.w;
            xg[p][4] = a1.x; xg[p][5] = a1.y; xg[p][6] = a1.z; xg[p][7] = a1.w;
            eg[p][0] = e0.x; eg[p][1] = e0.y; eg[p][2] = e0.z; eg[p][3] = e0.w;
            eg[p][4] = e1.x; eg[p][5] = e1.y; eg[p][6] = e1.z; eg[p][7] = e1.w;
        }

        // tail waits: chunks 4..7 (second commits of all 4 stages)
        #pragma unroll
        for (int c = 4; c < 8; c++) {
            int s = c & 3;
            MBAR_WAIT(doneu[s], (unsigned)(dph[s] & 1));
            dph[s]++;
        }
        TC_FENCE_AFTER();

        // next step's W prefetch, overlapped with epilogue + barrier
        if (t < Tlen - 1) { FILL_B(0, 0); FILL_B(1, 1); FILL_B(2, 2); }

        unsigned dr[32];
        TC_LD32(dr, tmem + (wid >> 2) * 32);
        TC_WAIT_LD();
        TC_FENCE_BEFORE();

        __half hh[8];
        #pragma unroll
        for (int jl = 0; jl < 8; jl++) {
            float ig = __uint_as_float(dr[4 * jl + 0]) + xg[0][jl] + eg[0][jl];
            float fg = __uint_as_float(dr[4 * jl + 1]) + xg[1][jl] + eg[1][jl];
            float gg = __uint_as_float(dr[4 * jl + 2]) + xg[2][jl] + eg[2][jl];
            float og = __uint_as_float(dr[4 * jl + 3]) + xg[3][jl] + eg[3][jl];
            ig = fsig(ig); fg = fsig(fg); og = fsig(og); gg = ftanh(gg);
            float cv = fg * creg[jl] + ig * gg;
            creg[jl] = cv;
            hh[jl] = __float2half_rn(og * ftanh(cv));
        }
        {
            size_t o = (size_t)b * Hdim + jb + jh;
            *(uint4*)&hout[o] = *(uint4*)&hh[0];
            size_t ho = ((size_t)t * Bsz + b) * Hdim + jb + jh;
            *(uint4*)&hs[ho] = *(uint4*)&hh[0];
        }

        if (t < Tlen - 1) {
            __syncthreads();
            if (tid == 0) {
                __threadfence();
                unsigned old = atomicAdd(&g_arr2[half], 1);
                if (old == 63) {
                    g_arr2[half] = 0;
                    asm volatile("st.release.gpu.b32 [%0], %1;"
                                 :: "l"(&g_gen2[half]), "r"((unsigned)(t + 1)) : "memory");
                } else {
                    unsigned g;
                    do {
                        asm volatile("ld.acquire.gpu.b32 %0, [%1];"
                                     : "=r"(g) : "l"(&g_gen2[half]) : "memory");
                        if (g < (unsigned)(t + 1)) __nanosleep(32);
                    } while (g < (unsigned)(t + 1));
                }
            }
            __syncthreads();
        }
    }

    __syncthreads();
    if (wid == 0) TC_DEALLOC(tmem, 512);
    #undef FILL_B
    #undef FILL_A

#else
    // ===================== mma.sync fallback (fp16 single-term) =====================
    extern __shared__ __align__(1024) unsigned char dsm[];
    unsigned smem_u = smem_u32(dsm);
    float* Gs = (float*)dsm;

    const int bx = blockIdx.x;
    const int j0 = (bx & 31) * 32;
    const int b0 = (bx >> 5) * 64;
    const int gcol0 = j0 * 4;
    const int tid = threadIdx.x;
    const int lane = tid & 31, w = tid >> 5;
    const int wm = w & 1, wn = w >> 1;
    const int qr = lane >> 2, qk = (lane & 3) * 2;
    const int ar = tid >> 2, akc = (tid & 3) * 8;
    const int br = tid >> 1, bkc = (tid & 1) * 16;

    const __half* gB = whh + (size_t)(gcol0 + br) * Hdim + bkc;

    float creg[8];
    #pragma unroll
    for (int i = 0; i < 8; i++) {
        int idx = tid + i * 256;
        creg[i] = c0[(b0 + (idx >> 5)) * Hdim + j0 + (idx & 31)];
    }

    for (int t = 0; t < Tlen; t++) {
        const __half* hin = (t & 1) ? hB : hA;
        __half* hout      = (t & 1) ? hA : hB;

        float acc[2][4][4];
        #pragma unroll
        for (int mt = 0; mt < 2; mt++)
            #pragma unroll
            for (int nt = 0; nt < 4; nt++)
                #pragma unroll
                for (int q = 0; q < 4; q++) acc[mt][nt][q] = 0.f;

        mma_mainloop1(hin + (size_t)(b0 + ar) * Hdim + akc, gB, smem_u, tid, acc);

        __syncthreads();
        #pragma unroll
        for (int mt = 0; mt < 2; mt++)
            #pragma unroll
            for (int nt = 0; nt < 4; nt++) {
                int r = wm * 32 + mt * 16 + qr;
                int cc = wn * 32 + nt * 8 + qk;
                *(float2*)&Gs[r * 132 + cc]       = make_float2(acc[mt][nt][0], acc[mt][nt][1]);
                *(float2*)&Gs[(r + 8) * 132 + cc] = make_float2(acc[mt][nt][2], acc[mt][nt][3]);
            }
        __syncthreads();

        #pragma unroll
        for (int i = 0; i < 8; i++) {
            int idx = tid + i * 256;
            int bl = idx >> 5, jj = idx & 31;
            float4 gv = *(const float4*)&Gs[bl * 132 + jj * 4];
            int b = b0 + bl, j = j0 + jj;
            int tok = (t == 0) ? 0 : atom_truth[b * Tlen + (t - 1)];
            const float* xp = xpart + (size_t)b * G4 + j;
            const float* ep = embproj + (size_t)tok * G4 + j;
            float ig = gv.x + xp[0]        + ep[0];
            float fg = gv.y + xp[Hdim]     + ep[Hdim];
            float gg = gv.z + xp[2 * Hdim] + ep[2 * Hdim];
            float og = gv.w + xp[3 * Hdim] + ep[3 * Hdim];
            ig = fsig(ig); fg = fsig(fg); og = fsig(og); gg = ftanh(gg);
            float cv = fg * creg[i] + ig * gg;
            creg[i] = cv;
            __half hv = __float2half_rn(og * ftanh(cv));
            hout[b * Hdim + j] = hv;
            hs[((size_t)t * Bsz + b) * Hdim + j] = hv;
        }

        if (t < Tlen - 1) grid_sync(tid, (unsigned)(t + 1));
    }
#endif
}

// ---------------------------------------------------------------------------
// Logits GEMM, tcgen05: C[16384,512] = hs @ W_out^T + b_out.
// Single-term fp16. Tiles 128m x 64n; grid (8, 128).
// ---------------------------------------------------------------------------
__global__ __launch_bounds__(256, 1) void logits_tc(
    const __half* __restrict__ A_g,
    const __half* __restrict__ B_g,
    float* __restrict__ C,
    const float* __restrict__ bias)
{
#if defined(__CUDA_ARCH_FEAT_SM100_ALL)
    extern __shared__ __align__(1024) unsigned char dsm[];
    __shared__ unsigned s_tmem;
    __shared__ __align__(8) unsigned long long s_mbar[N_STG];

    const unsigned smem_u = smem_u32(dsm);
    const int tid = threadIdx.x;
    const int wid = tid >> 5, lane = tid & 31;
    const int n0 = blockIdx.x * 64;
    const int m0 = blockIdx.y * 128;

    if (tid == 0) {
        #pragma unroll
        for (int i = 0; i < N_STG; i++) MBAR_INIT(smem_u32(&s_mbar[i]), 1);
    }
    __syncthreads();
    if (wid == 0) TC_ALLOC(smem_u32(&s_tmem), 512);
    __syncthreads();
    const unsigned tmem = s_tmem;
    unsigned mbu[N_STG];
    #pragma unroll
    for (int i = 0; i < N_STG; i++) mbu[i] = smem_u32(&s_mbar[i]);
    int ph[N_STG] = {0, 0, 0, 0, 0, 0, 0, 0};

    const int ra = tid >> 1, ca = (tid & 1) * 4;
    const int rb = tid >> 2, cb2 = (tid & 3) * 2;
    const int ram = ra & 7, rbm = rb & 7;
    const __half* Asrc = A_g + (size_t)(m0 + ra) * Hdim;
    const __half* Bsrc = B_g + (size_t)(n0 + rb) * Hdim;

    #define LFILL(kc_, st_) do { \
        unsigned ab = smem_u + (st_) * STG_SZ; \
        const __half* sh = Asrc + (kc_) * 64; \
        _Pragma("unroll") \
        for (int c = 0; c < 4; c++) { \
            int cc = ca + c; \
            unsigned d = ra * 128 + ((cc ^ ram) * 16); \
            CP16(ab + d, sh + cc * 8); \
        } \
        const __half* bs = Bsrc + (kc_) * 64; \
        _Pragma("unroll") \
        for (int c = 0; c < 2; c++) { \
            int cc = cb2 + c; \
            unsigned d = rb * 128 + ((cc ^ rbm) * 16); \
            CP16(ab + 16384 + d, bs + cc * 8); \
        } \
        CPCOMMIT(); \
    } while (0)

    LFILL(0, 0); LFILL(1, 1); LFILL(2, 2); LFILL(3, 3);
    LFILL(4, 4); LFILL(5, 5); LFILL(6, 6);

    for (int kc = 0; kc < 16; kc++) {
        if (kc <= 9)       { CPWAIT(6); }
        else if (kc == 10) { CPWAIT(5); }
        else if (kc == 11) { CPWAIT(4); }
        else if (kc == 12) { CPWAIT(3); }
        else if (kc == 13) { CPWAIT(2); }
        else if (kc == 14) { CPWAIT(1); }
        else               { CPWAIT(0); }
        __syncthreads();
        if (wid == 0 && elect1()) {
            unsigned sb = smem_u + (kc % N_STG) * STG_SZ;
            unsigned long long ad = mk_desc(sb);
            unsigned long long bd = mk_desc(sb + 16384);
            #pragma unroll
            for (int ks = 0; ks < 4; ks++) {
                unsigned en0 = (kc == 0 && ks == 0) ? 0u : 1u;
                tc_mma_f16_ss(tmem, ad + ks * 2, bd + ks * 2, IDESC_F16, en0);
            }
            TC_COMMIT(mbu[kc % N_STG]);
        }
        if (kc + 7 < 16) {
            if (kc >= 1) {
                int s = (kc - 1) % N_STG;
                MBAR_WAIT(mbu[s], (unsigned)(ph[s] & 1));
                ph[s]++;
            }
            LFILL(kc + 7, (kc + 7) % N_STG);
        }
    }
    #pragma unroll
    for (int c = 8; c < 16; c++) {
        int s = c % N_STG;
        MBAR_WAIT(mbu[s], (unsigned)(ph[s] & 1));
        ph[s]++;
    }
    TC_FENCE_AFTER();

    unsigned dr[32];
    TC_LD32(dr, tmem + (wid >> 2) * 32);
    TC_WAIT_LD();
    TC_FENCE_BEFORE();

    // stage to smem [128][65] then coalesced write with bias
    float* S = (float*)dsm;
    {
        int r = (wid & 3) * 32 + lane;
        int cb = (wid >> 2) * 32;
        #pragma unroll
        for (int c = 0; c < 32; c++) S[r * 65 + cb + c] = __uint_as_float(dr[c]);
    }
    __syncthreads();
    #pragma unroll
    for (int q = 0; q < 8; q++) {
        int idx = tid + q * 256;
        int rr = idx >> 4, c4 = (idx & 15) * 4;
        float4 bv = *(const float4*)&bias[n0 + c4];
        float4 v;
        v.x = S[rr * 65 + c4 + 0] + bv.x;
        v.y = S[rr * 65 + c4 + 1] + bv.y;
        v.z = S[rr * 65 + c4 + 2] + bv.z;
        v.w = S[rr * 65 + c4 + 3] + bv.w;
        *(float4*)&C[(size_t)(m0 + rr) * NTAG + n0 + c4] = v;
    }
    __syncthreads();
    if (wid == 0) TC_DEALLOC(tmem, 512);
    #undef LFILL
#endif
}

// ---------------------------------------------------------------------------
// Logits fallback (mma.sync) — no-ops when tcgen05 cubin active.
// ---------------------------------------------------------------------------
__global__ __launch_bounds__(256) void logits_mma(
    const __half* __restrict__ A_g,
    const __half* __restrict__ B_g,
    float* __restrict__ C,
    const float* __restrict__ bias)
{
    if (g_use_tc) return;
    extern __shared__ __align__(16) unsigned char dsm2[];
    unsigned smem_u = (unsigned)__cvta_generic_to_shared(dsm2);

    const int n0 = blockIdx.x * 128;
    const int m0 = blockIdx.y * 64;
    const int tid = threadIdx.x;
    const int lane = tid & 31, w = tid >> 5;
    const int wm = w & 1, wn = w >> 1;
    const int qr = lane >> 2, qk = (lane & 3) * 2;
    const int ar = tid >> 2, akc = (tid & 3) * 8;
    const int br = tid >> 1, bkc = (tid & 1) * 16;

    float acc[2][4][4];
    #pragma unroll
    for (int mt = 0; mt < 2; mt++)
        #pragma unroll
        for (int nt = 0; nt < 4; nt++)
            #pragma unroll
            for (int q = 0; q < 4; q++) acc[mt][nt][q] = 0.f;

    mma_mainloop1(A_g + (size_t)(m0 + ar) * Hdim + akc,
                  B_g + (size_t)(n0 + br) * Hdim + bkc,
                  smem_u, tid, acc);

    #pragma unroll
    for (int mt = 0; mt < 2; mt++)
        #pragma unroll
        for (int nt = 0; nt < 4; nt++) {
            int m = m0 + wm * 32 + mt * 16 + qr;
            int n = n0 + wn * 32 + nt * 8 + qk;
            float b0v = bias[n], b1v = bias[n + 1];
            *(float2*)&C[(size_t)m * NTAG + n] =
                make_float2(acc[mt][nt][0] + b0v, acc[mt][nt][1] + b1v);
            *(float2*)&C[(size_t)(m + 8) * NTAG + n] =
                make_float2(acc[mt][nt][2] + b0v, acc[mt][nt][3] + b1v);
        }
}

// ---------------------------------------------------------------------------
// Mask detection / NLL / reduction
// ---------------------------------------------------------------------------
__global__ void detect_mask(const unsigned* __restrict__ m)
{
    __shared__ int isByte, isFloat;
    if (threadIdx.x == 0) { isByte = 0; isFloat = 0; }
    __syncthreads();
    for (int i = threadIdx.x; i < (Bsz * Tlen) / 4; i += blockDim.x) {
        unsigned v = m[i];
        if (v == 0x3F800000u) isFloat = 1;
        else if (v > 1u) isByte = 1;
    }
    __syncthreads();
    if (threadIdx.x == 0) g_mask_mode = isFloat ? 2 : (isByte ? 1 : 0);
}

__global__ __launch_bounds__(128) void nll_rows(
    const float* __restrict__ logits,
    const int* __restrict__ atom_truth,
    const void* __restrict__ atom_mask,
    float* __restrict__ rownll,
    float* __restrict__ rowmask)
{
    const int r = blockIdx.x;
    const int t = r >> 8;
    const int b = r & 255;
    const float* row = logits + (size_t)r * NTAG;
    const int tid = threadIdx.x;
    __shared__ float red[128];

    float mx = -1e30f;
    for (int i = tid; i < NTAG; i += 128) mx = fmaxf(mx, row[i]);
    red[tid] = mx; __syncthreads();
    for (int s = 64; s > 0; s >>= 1) {
        if (tid < s) red[tid] = fmaxf(red[tid], red[tid + s]);
        __syncthreads();
    }
    mx = red[0]; __syncthreads();

    float sm = 0.f;
    for (int i = tid; i < NTAG; i += 128) sm += __expf(row[i] - mx);
    red[tid] = sm; __syncthreads();
    for (int s = 64; s > 0; s >>= 1) {
        if (tid < s) red[tid] += red[tid + s];
        __syncthreads();
    }

    if (tid == 0) {
        int tgt = atom_truth[b * Tlen + t];
        float lp = row[tgt] - mx - logf(red[0]);
        int mode = g_mask_mode;
        float m;
        if (mode == 2)      m = (((const float*)atom_mask)[b * Tlen + t] != 0.f) ? 1.f : 0.f;
        else if (mode == 1) m = (((const unsigned char*)atom_mask)[b * Tlen + t] != 0) ? 1.f : 0.f;
        else                m = (((const int*)atom_mask)[b * Tlen + t] != 0) ? 1.f : 0.f;
        rownll[r]  = -lp * m;
        rowmask[r] = m;
    }
}

__global__ __launch_bounds__(256) void final_reduce(
    const float* __restrict__ rownll,
    const float* __restrict__ rowmask,
    float* __restrict__ out)
{
    __shared__ double rn[256], rm[256];
    double sn = 0.0, sm = 0.0;
    for (int i = threadIdx.x; i < Tlen * Bsz; i += 256) {
        sn += (double)rownll[i];
        sm += (double)rowmask[i];
    }
    rn[threadIdx.x] = sn; rm[threadIdx.x] = sm;
    __syncthreads();
    for (int s = 128; s > 0; s >>= 1) {
        if (threadIdx.x < s) {
            rn[threadIdx.x] += rn[threadIdx.x + s];
            rm[threadIdx.x] += rm[threadIdx.x + s];
        }
        __syncthreads();
    }
    if (threadIdx.x == 0) out[0] = (float)(rn[0] / rm[0]);
}

// ---------------------------------------------------------------------------
// Launch
// ---------------------------------------------------------------------------
extern "C" void kernel_launch(void* const* d_in, const int* in_sizes, int n_in,
                              void* d_out, int out_size)
{
    const float* x      = (const float*)d_in[0];
    const int*   atomtr = (const int*)d_in[1];
    const void*  mask   = d_in[2];
    const float* emb    = (const float*)d_in[3];
    const float* W_ih   = (const float*)d_in[4];
    const float* W_hh   = (const float*)d_in[5];
    const float* b_ih   = (const float*)d_in[6];
    const float* b_hh   = (const float*)d_in[7];
    const float* W_out  = (const float*)d_in[8];
    const float* b_out  = (const float*)d_in[9];
    const float* h0     = (const float*)d_in[10];
    const float* c0     = (const float*)d_in[11];

    float* sc = nullptr;
    cudaGetSymbolAddress((void**)&sc, g_scratch);
    float* xpart   = sc + 0;
    float* embproj = sc + 1048576;
    float* logits  = sc + 3407872;
    float* rownll  = sc + 11796480;
    float* rowmask = sc + 11812864;
    __half* hb = (__half*)(sc + 11829248);
    __half* whh  = hb + 0;
    __half* wout = hb + 8388608;
    __half* hA   = hb + 9437184;
    __half* hB   = hb + 9699328;
    __half* hs   = hb + 9961472;

    const int DSMEM_LOGTC = N_STG * STG_SZ;   // 196608
    const int DSMEM_LOG   = 3 * 15360;        // 46080
    static int attr_done = 0;
    if (!attr_done) {
        cudaFuncSetAttribute(lstm_seq,   cudaFuncAttributeMaxDynamicSharedMemorySize, DSMEM_LSTM);
        cudaFuncSetAttribute(logits_tc,  cudaFuncAttributeMaxDynamicSharedMemorySize, DSMEM_LOGTC);
        cudaFuncSetAttribute(logits_mma, cudaFuncAttributeMaxDynamicSharedMemorySize, DSMEM_LOG);
        attr_done = 1;
    }

    detect_mask<<<1, 256>>>((const unsigned*)mask);
    init_bar<<<1, 1>>>();

    // one-time weight / state conversions (single fp16)
    interleave_whh<<<4096, 256>>>(W_hh, whh);
    conv16<<<512, 256>>>(W_out, wout);
    conv16<<<256, 256>>>(h0, hA);

    // merged projection: xpart + embproj in one launch (grid 64x6)
    proj_dual<<<dim3(G4 / 64, 6), 256>>>(x, emb, W_ih, xpart, embproj, b_ih, b_hh);

    // all 64 LSTM steps in one persistent kernel
    lstm_seq<<<128, 256, DSMEM_LSTM>>>(
        hA, hB, c0, xpart, embproj, hs, whh, atomtr);

    // logits = hs @ W_out^T + b_out   [16384, 512]  (exactly one of these runs)
    logits_tc<<<dim3(NTAG / 64, (Tlen * Bsz) / 128), 256, DSMEM_LOGTC>>>(
        hs, wout, logits, b_out);
    logits_mma<<<dim3(NTAG / 128, (Tlen * Bsz) / 64), 256, DSMEM_LOG>>>(
        hs, wout, logits, b_out);

    nll_rows<<<Tlen * Bsz, 128>>>(logits, atomtr, mask, rownll, rowmask);
    final_reduce<<<1, 256>>>(rownll, rowmask, (float*)d_out);
}

// round 17
// speedup vs baseline: 1.0196x; 1.0196x over previous
#include <cuda_runtime.h>
#include <cuda_fp16.h>
#include <math.h>

#define Bsz  256
#define Tlen 64
#define Hdim 1024
#define Xdim 512
#define Edim 256
#define DIN  768
#define G4   4096
#define NTAG 512

// ---- scratch layout ----
// floats:
//   xpart   @0          (1,048,576)
//   embproj @1,048,576  (2,097,152)
//   logits  @3,407,872  (8,388,608)   [fallback path only]
//   rownll  @11,796,480 (16,384)
//   rowmask @11,812,864 (16,384)
// fp16 region at float offset 11,829,248 (half-element offsets):
//   whh 0 (4,194,304)   wout 8,388,608 (524,288)
//   hA 9,437,184  hB 9,699,328
//   hs 9,961,472 (16,777,216)
__device__ float g_scratch[33849344];
__device__ int   g_mask_mode;
__device__ unsigned g_bar_arrive;
__device__ unsigned g_bar_gen;
__device__ unsigned g_arr2[2];
__device__ unsigned g_gen2[2];
__device__ int      g_use_tc;

// ---------------------------------------------------------------------------
// PTX helpers (portable)
// ---------------------------------------------------------------------------
#define MMA4F(c, a, b0_, b1_) \
    asm volatile("mma.sync.aligned.m16n8k16.row.col.f32.f16.f16.f32 " \
                 "{%0,%1,%2,%3},{%4,%5,%6,%7},{%8,%9},{%0,%1,%2,%3};" \
                 : "+f"((c)[0]), "+f"((c)[1]), "+f"((c)[2]), "+f"((c)[3]) \
                 : "r"((a)[0]), "r"((a)[1]), "r"((a)[2]), "r"((a)[3]), \
                   "r"(b0_), "r"(b1_))

#define LDSM4(r, addr) \
    asm volatile("ldmatrix.sync.aligned.m8n8.x4.shared.b16 {%0,%1,%2,%3}, [%4];" \
                 : "=r"((r)[0]), "=r"((r)[1]), "=r"((r)[2]), "=r"((r)[3]) \
                 : "r"(addr))

#define CP16(dst, src) \
    asm volatile("cp.async.cg.shared.global [%0], [%1], 16;" :: "r"(dst), "l"(src))
#define CPCOMMIT() asm volatile("cp.async.commit_group;" ::: "memory")
#define CPWAIT(n)  asm volatile("cp.async.wait_group %0;" :: "n"(n) : "memory")
#define CP_ARRIVE(mb) \
    asm volatile("cp.async.mbarrier.arrive.noinc.shared.b64 [%0];" :: "r"(mb) : "memory")

#define FFMA2(d, a, b) asm("fma.rn.f32x2 %0, %1, %2, %0;" : "+l"(d) : "l"(a), "l"(b))
union F2U { unsigned long long u; float2 f; };
__device__ __forceinline__ unsigned long long dup2(float a) {
    unsigned x = __float_as_uint(a);
    return ((unsigned long long)x << 32) | (unsigned long long)x;
}

__device__ __forceinline__ unsigned smem_u32(const void* p) {
    return (unsigned)__cvta_generic_to_shared(p);
}

// fast activations (safe at +/-inf)
__device__ __forceinline__ float fsig(float x) {
    return __fdividef(1.f, 1.f + __expf(-x));
}
__device__ __forceinline__ float ftanh(float x) {
    return 1.f - __fdividef(2.f, __expf(2.f * x) + 1.f);
}

// ---------------------------------------------------------------------------
// tcgen05 helpers — ONLY compiled on the sm_100a pass.
// ---------------------------------------------------------------------------
#if defined(__CUDA_ARCH_FEAT_SM100_ALL)
__device__ __forceinline__ bool elect1() {
    unsigned p;
    asm volatile("{\n\t.reg .pred p;\n\telect.sync _|p, 0xFFFFFFFF;\n\tselp.b32 %0,1,0,p;\n\t}"
                 : "=r"(p));
    return p != 0;
}
__device__ __forceinline__ unsigned long long mk_desc(unsigned addr) {
    // SW128, version=1 (Blackwell), SBO=64, LBO=1 (K-major, 128B rows)
    return 0x4000404000010000ULL | ((unsigned long long)(addr >> 4) & 0x3FFF);
}
__device__ __forceinline__ void tc_mma_f16_ss(unsigned d, unsigned long long ad,
                                              unsigned long long bd, unsigned idesc,
                                              unsigned en)
{
    asm volatile(
        "{\n\t.reg .pred p;\n\tsetp.ne.u32 p, %5, 0;\n\t"
        "tcgen05.mma.cta_group::1.kind::f16 [%0], %1, %2, %3, {%4, %4, %4, %4}, p;\n\t}"
        :: "r"(d), "l"(ad), "l"(bd), "r"(idesc), "r"(0u), "r"(en)
        : "memory");
}
#define TC_ALLOC(smaddr, n) \
    asm volatile("tcgen05.alloc.cta_group::1.sync.aligned.shared::cta.b32 [%0], %1;" \
                 :: "r"(smaddr), "r"((unsigned)(n)) : "memory")
#define TC_DEALLOC(base, n) \
    asm volatile("tcgen05.dealloc.cta_group::1.sync.aligned.b32 %0, %1;" \
                 :: "r"(base), "r"((unsigned)(n)))
#define TC_COMMIT(mb) \
    asm volatile("tcgen05.commit.cta_group::1.mbarrier::arrive::one.shared::cluster.b64 [%0];" \
                 :: "r"(mb) : "memory")
#define TC_FENCE_AFTER()  asm volatile("tcgen05.fence::after_thread_sync;" ::: "memory")
#define TC_FENCE_BEFORE() asm volatile("tcgen05.fence::before_thread_sync;" ::: "memory")
#define TC_WAIT_LD()      asm volatile("tcgen05.wait::ld.sync.aligned;" ::: "memory")

#define MBAR_INIT(mb, cnt) \
    asm volatile("mbarrier.init.shared.b64 [%0], %1;" :: "r"(mb), "r"((unsigned)(cnt)) : "memory")
#define MBAR_WAIT(mb, par) do { \
    unsigned _m = (mb), _p = (par), _d; \
    asm volatile("{\n\t.reg .pred p;\n\t" \
                 "mbarrier.try_wait.parity.acquire.cta.shared::cta.b64 p, [%1], %2;\n\t" \
                 "selp.b32 %0,1,0,p;\n\t}" : "=r"(_d) : "r"(_m), "r"(_p) : "memory"); \
    if (!_d) { \
        asm volatile("{\n\t.reg .pred P1;\n\t" \
                     "WL%=:\n\t" \
                     "mbarrier.try_wait.parity.acquire.cta.shared::cta.b64 P1, [%0], %1, 0x989680;\n\t" \
                     "@P1 bra.uni WD%=;\n\tbra.uni WL%=;\n\tWD%=:\n\t}" \
                     :: "r"(_m), "r"(_p) : "memory"); \
    } \
} while(0)

#define TC_LD32(r, addr) \
    asm volatile("tcgen05.ld.sync.aligned.32x32b.x32.b32 " \
        "{%0,%1,%2,%3,%4,%5,%6,%7,%8,%9,%10,%11,%12,%13,%14,%15," \
        "%16,%17,%18,%19,%20,%21,%22,%23,%24,%25,%26,%27,%28,%29,%30,%31}, [%32];" \
        : "=r"((r)[0]),"=r"((r)[1]),"=r"((r)[2]),"=r"((r)[3]), \
          "=r"((r)[4]),"=r"((r)[5]),"=r"((r)[6]),"=r"((r)[7]), \
          "=r"((r)[8]),"=r"((r)[9]),"=r"((r)[10]),"=r"((r)[11]), \
          "=r"((r)[12]),"=r"((r)[13]),"=r"((r)[14]),"=r"((r)[15]), \
          "=r"((r)[16]),"=r"((r)[17]),"=r"((r)[18]),"=r"((r)[19]), \
          "=r"((r)[20]),"=r"((r)[21]),"=r"((r)[22]),"=r"((r)[23]), \
          "=r"((r)[24]),"=r"((r)[25]),"=r"((r)[26]),"=r"((r)[27]), \
          "=r"((r)[28]),"=r"((r)[29]),"=r"((r)[30]),"=r"((r)[31]) \
        : "r"(addr))

// idesc: f32 accum, f16 a/b, M=128, N=64
#define IDESC_F16 0x08100010u
#endif // __CUDA_ARCH_FEAT_SM100_ALL

// ---------------------------------------------------------------------------
// Conversion kernels (single fp16)
// ---------------------------------------------------------------------------
__global__ void interleave_whh(const float* __restrict__ W, __half* __restrict__ out)
{
    int c = blockIdx.x;                 // gate-interleaved row c = j*4 + g
    int j = c >> 2, g = c & 3;
    const float* src = W + (size_t)(g * Hdim + j) * Hdim;
    int k = threadIdx.x * 4;
    float4 v = *(const float4*)&src[k];
    size_t o = (size_t)c * Hdim + k;
    out[o + 0] = __float2half_rn(v.x);
    out[o + 1] = __float2half_rn(v.y);
    out[o + 2] = __float2half_rn(v.z);
    out[o + 3] = __float2half_rn(v.w);
}

__global__ void conv16(const float* __restrict__ src, __half* __restrict__ dst)
{
    int i = (blockIdx.x * 256 + threadIdx.x) * 4;
    float4 v = *(const float4*)&src[i];
    dst[i + 0] = __float2half_rn(v.x);
    dst[i + 1] = __float2half_rn(v.y);
    dst[i + 2] = __float2half_rn(v.z);
    dst[i + 3] = __float2half_rn(v.w);
}

// ---------------------------------------------------------------------------
// Merged projection GEMM (f32x2): one launch computes
//   by<2 : xpart[m0..m0+127]   = x @ W_ih[:, :512]^T + b_ih + b_hh
//   by>=2: embproj[m0..m0+127] = emb @ W_ih[:, 512:768]^T
// Grid (64, 6), 256 threads.
// ---------------------------------------------------------------------------
__global__ __launch_bounds__(256) void proj_dual(
    const float* __restrict__ x,
    const float* __restrict__ emb,
    const float* __restrict__ W_ih,
    float* __restrict__ xpart,
    float* __restrict__ embproj,
    const float* __restrict__ b_ih,
    const float* __restrict__ b_hh)
{
    const int by = blockIdx.y;
    const float* A; const float* Bm; float* C;
    const float *bias0, *bias1;
    int lda, K, m0;
    if (by < 2) {
        A = x;  lda = Xdim; K = Xdim; m0 = by * 128;
        Bm = W_ih; C = xpart; bias0 = b_ih; bias1 = b_hh;
    } else {
        A = emb; lda = Edim; K = Edim; m0 = (by - 2) * 128;
        Bm = W_ih + Xdim; C = embproj; bias0 = nullptr; bias1 = nullptr;
    }
    const int ldb = DIN, ldc = G4;

    __shared__ unsigned long long As2[16][128];
    __shared__ float Bs[16][64];
    const int n0 = blockIdx.x * 64;
    const int tid = threadIdx.x;
    const int rg = tid >> 4;
    const int cg = tid & 15;
    unsigned long long acc[8][2];
    #pragma unroll
    for (int i = 0; i < 8; i++) { acc[i][0] = 0ull; acc[i][1] = 0ull; }
    const int fm = tid >> 2;
    const int fk = (tid & 3) * 4;

    for (int k0 = 0; k0 < K; k0 += 16) {
        __syncthreads();
        #pragma unroll
        for (int half = 0; half < 2; half++) {
            int m = fm + half * 64;
            float4 v = *(const float4*)&A[(size_t)(m0 + m) * lda + k0 + fk];
            As2[fk + 0][m] = dup2(v.x);
            As2[fk + 1][m] = dup2(v.y);
            As2[fk + 2][m] = dup2(v.z);
            As2[fk + 3][m] = dup2(v.w);
        }
        {
            float4 v = *(const float4*)&Bm[(size_t)(n0 + fm) * ldb + k0 + fk];
            Bs[fk + 0][fm] = v.x; Bs[fk + 1][fm] = v.y;
            Bs[fk + 2][fm] = v.z; Bs[fk + 3][fm] = v.w;
        }
        __syncthreads();
        #pragma unroll
        for (int k = 0; k < 16; k++) {
            const ulonglong2* ap = (const ulonglong2*)&As2[k][rg * 8];
            ulonglong2 bv = *(const ulonglong2*)&Bs[k][cg * 4];
            #pragma unroll
            for (int i2 = 0; i2 < 4; i2++) {
                ulonglong2 a = ap[i2];
                FFMA2(acc[2 * i2 + 0][0], a.x, bv.x);
                FFMA2(acc[2 * i2 + 0][1], a.x, bv.y);
                FFMA2(acc[2 * i2 + 1][0], a.y, bv.x);
                FFMA2(acc[2 * i2 + 1][1], a.y, bv.y);
            }
        }
    }
    #pragma unroll
    for (int i = 0; i < 8; i++) {
        int m = m0 + rg * 8 + i;
        #pragma unroll
        for (int p = 0; p < 2; p++) {
            int n = n0 + cg * 4 + p * 2;
            F2U u; u.u = acc[i][p];
            float v0 = u.f.x, v1 = u.f.y;
            if (bias0) { v0 += bias0[n]; v1 += bias0[n + 1]; }
            if (bias1) { v0 += bias1[n]; v1 += bias1[n + 1]; }
            *(float2*)&C[(size_t)m * ldc + n] = make_float2(v0, v1);
        }
    }
}

// ---------------------------------------------------------------------------
// mma.sync fallback mainloop: single-term fp16. 64m x 128n.
// 3 stages x 15360 B: A[64][40]@0, B[128][40]@5120.
// ---------------------------------------------------------------------------
__device__ __forceinline__ void mma_mainloop1(
    const __half* __restrict__ gA, const __half* __restrict__ gB,
    unsigned smem_u, int tid, float acc[2][4][4])
{
    const int lane = tid & 31, w = tid >> 5;
    const int wm = w & 1, wn = w >> 1;
    const int lrow = (lane & 7) + ((lane >> 3) & 1) * 8;
    const int lcol = (lane >> 4) * 8;
    const unsigned aoff = ((wm * 32 + lrow) * 40 + lcol) * 2;
    const unsigned boff = ((wn * 32 + lrow) * 40 + lcol) * 2;

    const int ar = tid >> 2;
    const int br = tid >> 1;
    const unsigned dA  = (ar * 40 + (tid & 3) * 8) * 2;
    const unsigned dB0 = (br * 40 + (tid & 1) * 16) * 2;
    const unsigned dB1 = dB0 + 16;

    #pragma unroll
    for (int s = 0; s < 2; s++) {
        unsigned sb = smem_u + s * 15360;
        int k0 = s * 32;
        CP16(sb + dA,         gA + k0);
        CP16(sb + 5120 + dB0, gB + k0);
        CP16(sb + 5120 + dB1, gB + k0 + 8);
        CPCOMMIT();
    }

    for (int i = 0; i < 32; i++) {
        if (i < 31) { CPWAIT(1); } else { CPWAIT(0); }
        __syncthreads();
        if (i + 2 < 32) {
            unsigned sb = smem_u + ((i + 2) % 3) * 15360;
            int k0 = (i + 2) * 32;
            CP16(sb + dA,         gA + k0);
            CP16(sb + 5120 + dB0, gB + k0);
            CP16(sb + 5120 + dB1, gB + k0 + 8);
            CPCOMMIT();
        }
        unsigned sb = smem_u + (i % 3) * 15360;
        #pragma unroll
        for (int kh = 0; kh < 2; kh++) {
            const unsigned kb = kh * 32;
            unsigned a0[4], a1[4];
            LDSM4(a0, sb + aoff + kb);
            LDSM4(a1, sb + aoff + 1280 + kb);
            unsigned bh0[4], bh1[4];
            LDSM4(bh0, sb + 5120 + boff + kb);
            LDSM4(bh1, sb + 5120 + boff + 1280 + kb);
            #pragma unroll
            for (int nt = 0; nt < 4; nt++) {
                const unsigned* bhp = (nt < 2) ? bh0 : bh1;
                unsigned h0v = bhp[nt & 1], h1v = bhp[(nt & 1) + 2];
                MMA4F(acc[0][nt], a0, h0v, h1v);
                MMA4F(acc[1][nt], a1, h0v, h1v);
            }
        }
    }
}

// ---------------------------------------------------------------------------
// Barriers
// ---------------------------------------------------------------------------
__global__ void init_bar() {
    g_bar_arrive = 0; g_bar_gen = 0;
    g_arr2[0] = 0; g_arr2[1] = 0;
    g_gen2[0] = 0; g_gen2[1] = 0;
#if defined(__CUDA_ARCH_FEAT_SM100_ALL)
    g_use_tc = 1;
#else
    g_use_tc = 0;
#endif
}

__device__ __forceinline__ void grid_sync(int tid, unsigned gen)
{
    __syncthreads();
    if (tid == 0) {
        __threadfence();
        unsigned a = atomicAdd(&g_bar_arrive, 1);
        if (a == 127) {
            g_bar_arrive = 0;
            __threadfence();
            atomicExch(&g_bar_gen, gen);
        } else {
            while (atomicAdd(&g_bar_gen, 0u) < gen) __nanosleep(64);
            __threadfence();
        }
    }
    __syncthreads();
}

// lstm tcgen05 stage: A0 16K @0, A1 @16384, B0 8K @32768, B1 @40960
#define LSTG 49152
#define LNS  4
#define DSMEM_LSTM (LNS * LSTG)   // 196608
// fused logits stage: A 16K @0, B 64K @16384
#define STGL 81920
#define DSMEM_LOGTC (2 * STGL)    // 163840

// ---------------------------------------------------------------------------
// Persistent LSTM sequence kernel — dual path (tcgen05 / mma.sync fallback).
// ---------------------------------------------------------------------------
__global__ __launch_bounds__(256, 1) void lstm_seq(
    __half* hA, __half* hB,
    const float* __restrict__ c0,
    const float* __restrict__ xpart,
    const float* __restrict__ embproj,
    __half* __restrict__ hs,
    const __half* __restrict__ whh,
    const int* __restrict__ atom_truth)
{
#if defined(__CUDA_ARCH_FEAT_SM100_ALL)
    extern __shared__ __align__(1024) unsigned char dsm[];
    __shared__ unsigned s_tmem;
    __shared__ __align__(8) unsigned long long s_full[LNS];
    __shared__ __align__(8) unsigned long long s_done[LNS];

    const unsigned smem_u = smem_u32(dsm);
    const int tid = threadIdx.x;
    const int wid = tid >> 5, lane = tid & 31;
    const int bx = blockIdx.x;
    const int half = bx >> 6;
    const int b0 = half * 128;
    const int ntb = bx & 63;
    const int c0g = ntb * 64;
    const int jb = ntb * 16;

    if (tid == 0) {
        #pragma unroll
        for (int i = 0; i < LNS; i++) {
            MBAR_INIT(smem_u32(&s_full[i]), 256);
            MBAR_INIT(smem_u32(&s_done[i]), 1);
        }
    }
    __syncthreads();
    if (wid == 0) TC_ALLOC(smem_u32(&s_tmem), 512);
    __syncthreads();
    const unsigned tmem = s_tmem;
    unsigned fullu[LNS], doneu[LNS];
    #pragma unroll
    for (int i = 0; i < LNS; i++) {
        fullu[i] = smem_u32(&s_full[i]);
        doneu[i] = smem_u32(&s_done[i]);
    }
    int mfp[LNS] = {0, 0, 0, 0};
    int dph[LNS] = {0, 0, 0, 0};

    const int ra = tid >> 1, ca = (tid & 1) * 4;
    const int rb = tid >> 2, cb2 = (tid & 3) * 2;
    const int ram = ra & 7, rbm = rb & 7;
    const __half* Bsrc = whh + (size_t)(c0g + rb) * Hdim;
    const __half* Asrc;

    const int b = b0 + (wid & 3) * 32 + lane;
    const int jh = (wid >> 2) * 8;
    float creg[8];
    {
        const float* cp = c0 + (size_t)b * Hdim + jb + jh;
        float4 v0 = *(const float4*)&cp[0];
        float4 v1 = *(const float4*)&cp[4];
        creg[0] = v0.x; creg[1] = v0.y; creg[2] = v0.z; creg[3] = v0.w;
        creg[4] = v1.x; creg[5] = v1.y; creg[6] = v1.z; creg[7] = v1.w;
    }

    #define FILL_B(kc_, st_) do { \
        unsigned ab = smem_u + (st_) * LSTG + 32768; \
        const __half* bs = Bsrc + (kc_) * 128; \
        _Pragma("unroll") \
        for (int sub = 0; sub < 2; sub++) { \
            _Pragma("unroll") \
            for (int c = 0; c < 2; c++) { \
                int cc = cb2 + c; \
                unsigned d = rb * 128 + ((cc ^ rbm) * 16); \
                CP16(ab + sub * 8192 + d, bs + sub * 64 + cc * 8); \
            } \
        } \
    } while (0)

    #define FILL_A(kc_, st_) do { \
        unsigned ab = smem_u + (st_) * LSTG; \
        const __half* sh = Asrc + (kc_) * 128; \
        _Pragma("unroll") \
        for (int sub = 0; sub < 2; sub++) { \
            _Pragma("unroll") \
            for (int c = 0; c < 4; c++) { \
                int cc = ca + c; \
                unsigned d = ra * 128 + ((cc ^ ram) * 16); \
                CP16(ab + sub * 16384 + d, sh + sub * 64 + cc * 8); \
            } \
        } \
    } while (0)

    FILL_B(0, 0); FILL_B(1, 1); FILL_B(2, 2);

    for (int t = 0; t < Tlen; t++) {
        const __half* hin = (t & 1) ? hB : hA;
        __half* hout      = (t & 1) ? hA : hB;
        Asrc = hin + (size_t)(b0 + ra) * Hdim;

        FILL_A(0, 0); CP_ARRIVE(fullu[0]);
        FILL_A(1, 1); CP_ARRIVE(fullu[1]);
        FILL_A(2, 2); CP_ARRIVE(fullu[2]);

        for (int kc = 0; kc < 8; kc++) {
            if (wid == 0 && elect1()) {
                int s = kc & 3;
                MBAR_WAIT(fullu[s], (unsigned)(mfp[s] & 1));
                mfp[s]++;
                unsigned sb = smem_u + s * LSTG;
                #pragma unroll
                for (int sub = 0; sub < 2; sub++) {
                    unsigned long long ad = mk_desc(sb + sub * 16384);
                    unsigned long long bd = mk_desc(sb + 32768 + sub * 8192);
                    #pragma unroll
                    for (int ks = 0; ks < 4; ks++) {
                        unsigned en0 = (kc == 0 && sub == 0 && ks == 0) ? 0u : 1u;
                        tc_mma_f16_ss(tmem, ad + ks * 2, bd + ks * 2, IDESC_F16, en0);
                    }
                }
                TC_COMMIT(doneu[s]);
            }
            if (kc + 3 < 8) {
                if (kc >= 1) {
                    int s = (kc - 1) & 3;
                    MBAR_WAIT(doneu[s], (unsigned)(dph[s] & 1));
                    dph[s]++;
                }
                int st = (kc + 3) & 3;
                FILL_A(kc + 3, st);
                FILL_B(kc + 3, st);
                CP_ARRIVE(fullu[st]);
            }
        }

        int tok = (t == 0) ? 0 : atom_truth[b * Tlen + (t - 1)];
        const float* xp = xpart + (size_t)b * G4 + jb + jh;
        const float* ep = embproj + (size_t)tok * G4 + jb + jh;
        float xg[4][8], eg[4][8];
        #pragma unroll
        for (int p = 0; p < 4; p++) {
            float4 a0 = *(const float4*)&xp[p * Hdim];
            float4 a1 = *(const float4*)&xp[p * Hdim + 4];
            float4 e0 = *(const float4*)&ep[p * Hdim];
            float4 e1 = *(const float4*)&ep[p * Hdim + 4];
            xg[p][0] = a0.x; xg[p][1] = a0.y; xg[p][2] = a0.z; xg[p][3] = a0.w;
            xg[p][4] = a1.x; xg[p][5] = a1.y; xg[p][6] = a1.z; xg[p][7] = a1.w;
            eg[p][0] = e0.x; eg[p][1] = e0.y; eg[p][2] = e0.z; eg[p][3] = e0.w;
            eg[p][4] = e1.x; eg[p][5] = e1.y; eg[p][6] = e1.z; eg[p][7] = e1.w;
        }

        #pragma unroll
        for (int c = 4; c < 8; c++) {
            int s = c & 3;
            MBAR_WAIT(doneu[s], (unsigned)(dph[s] & 1));
            dph[s]++;
        }
        TC_FENCE_AFTER();

        if (t < Tlen - 1) { FILL_B(0, 0); FILL_B(1, 1); FILL_B(2, 2); }

        unsigned dr[32];
        TC_LD32(dr, tmem + (wid >> 2) * 32);
        TC_WAIT_LD();
        TC_FENCE_BEFORE();

        __half hh[8];
        #pragma unroll
        for (int jl = 0; jl < 8; jl++) {
            float ig = __uint_as_float(dr[4 * jl + 0]) + xg[0][jl] + eg[0][jl];
            float fg = __uint_as_float(dr[4 * jl + 1]) + xg[1][jl] + eg[1][jl];
            float gg = __uint_as_float(dr[4 * jl + 2]) + xg[2][jl] + eg[2][jl];
            float og = __uint_as_float(dr[4 * jl + 3]) + xg[3][jl] + eg[3][jl];
            ig = fsig(ig); fg = fsig(fg); og = fsig(og); gg = ftanh(gg);
            float cv = fg * creg[jl] + ig * gg;
            creg[jl] = cv;
            hh[jl] = __float2half_rn(og * ftanh(cv));
        }
        {
            size_t o = (size_t)b * Hdim + jb + jh;
            *(uint4*)&hout[o] = *(uint4*)&hh[0];
        }

        // per-half grid barrier (hout must be visible before release)
        if (t < Tlen - 1) {
            __syncthreads();
            if (tid == 0) {
                __threadfence();
                unsigned old = atomicAdd(&g_arr2[half], 1);
                if (old == 63) {
                    g_arr2[half] = 0;
                    asm volatile("st.release.gpu.b32 [%0], %1;"
                                 :: "l"(&g_gen2[half]), "r"((unsigned)(t + 1)) : "memory");
                } else {
                    unsigned g;
                    do {
                        asm volatile("ld.acquire.gpu.b32 %0, [%1];"
                                     : "=r"(g) : "l"(&g_gen2[half]) : "memory");
                    } while (g < (unsigned)(t + 1));
                }
            }
            __syncthreads();
        }

        // hs store (consumed only post-kernel) moved off the barrier path
        {
            size_t ho = ((size_t)t * Bsz + b) * Hdim + jb + jh;
            *(uint4*)&hs[ho] = *(uint4*)&hh[0];
        }
    }

    __syncthreads();
    if (wid == 0) TC_DEALLOC(tmem, 512);
    #undef FILL_B
    #undef FILL_A

#else
    // ===================== mma.sync fallback (fp16 single-term) =====================
    extern __shared__ __align__(1024) unsigned char dsm[];
    unsigned smem_u = smem_u32(dsm);
    float* Gs = (float*)dsm;

    const int bx = blockIdx.x;
    const int j0 = (bx & 31) * 32;
    const int b0 = (bx >> 5) * 64;
    const int gcol0 = j0 * 4;
    const int tid = threadIdx.x;
    const int lane = tid & 31, w = tid >> 5;
    const int wm = w & 1, wn = w >> 1;
    const int qr = lane >> 2, qk = (lane & 3) * 2;
    const int ar = tid >> 2, akc = (tid & 3) * 8;
    const int br = tid >> 1, bkc = (tid & 1) * 16;

    const __half* gB = whh + (size_t)(gcol0 + br) * Hdim + bkc;

    float creg[8];
    #pragma unroll
    for (int i = 0; i < 8; i++) {
        int idx = tid + i * 256;
        creg[i] = c0[(b0 + (idx >> 5)) * Hdim + j0 + (idx & 31)];
    }

    for (int t = 0; t < Tlen; t++) {
        const __half* hin = (t & 1) ? hB : hA;
        __half* hout      = (t & 1) ? hA : hB;

        float acc[2][4][4];
        #pragma unroll
        for (int mt = 0; mt < 2; mt++)
            #pragma unroll
            for (int nt = 0; nt < 4; nt++)
                #pragma unroll
                for (int q = 0; q < 4; q++) acc[mt][nt][q] = 0.f;

        mma_mainloop1(hin + (size_t)(b0 + ar) * Hdim + akc, gB, smem_u, tid, acc);

        __syncthreads();
        #pragma unroll
        for (int mt = 0; mt < 2; mt++)
            #pragma unroll
            for (int nt = 0; nt < 4; nt++) {
                int r = wm * 32 + mt * 16 + qr;
                int cc = wn * 32 + nt * 8 + qk;
                *(float2*)&Gs[r * 132 + cc]       = make_float2(acc[mt][nt][0], acc[mt][nt][1]);
                *(float2*)&Gs[(r + 8) * 132 + cc] = make_float2(acc[mt][nt][2], acc[mt][nt][3]);
            }
        __syncthreads();

        #pragma unroll
        for (int i = 0; i < 8; i++) {
            int idx = tid + i * 256;
            int bl = idx >> 5, jj = idx & 31;
            float4 gv = *(const float4*)&Gs[bl * 132 + jj * 4];
            int b = b0 + bl, j = j0 + jj;
            int tok = (t == 0) ? 0 : atom_truth[b * Tlen + (t - 1)];
            const float* xp = xpart + (size_t)b * G4 + j;
            const float* ep = embproj + (size_t)tok * G4 + j;
            float ig = gv.x + xp[0]        + ep[0];
            float fg = gv.y + xp[Hdim]     + ep[Hdim];
            float gg = gv.z + xp[2 * Hdim] + ep[2 * Hdim];
            float og = gv.w + xp[3 * Hdim] + ep[3 * Hdim];
            ig = fsig(ig); fg = fsig(fg); og = fsig(og); gg = ftanh(gg);
            float cv = fg * creg[i] + ig * gg;
            creg[i] = cv;
            __half hv = __float2half_rn(og * ftanh(cv));
            hout[b * Hdim + j] = hv;
            hs[((size_t)t * Bsz + b) * Hdim + j] = hv;
        }

        if (t < Tlen - 1) grid_sync(tid, (unsigned)(t + 1));
    }
#endif
}

// ---------------------------------------------------------------------------
// FUSED logits + log-softmax + NLL, tcgen05 path.
// Grid 128: block computes rows m0..m0+127 x ALL 512 cols (8 N-tiles across
// full 512-col TMEM), K=1024 in 16 chunks of 64, 2-stage pipeline.
// Epilogue: stage D to smem fp32 (pad 517), per-row softmax/NLL in-block.
// No global logits buffer at all.
// ---------------------------------------------------------------------------
__global__ __launch_bounds__(256, 1) void logits_nll_tc(
    const __half* __restrict__ A_g,
    const __half* __restrict__ B_g,
    const float* __restrict__ bias,
    const int* __restrict__ atom_truth,
    const void* __restrict__ atom_mask,
    float* __restrict__ rownll,
    float* __restrict__ rowmask)
{
#if defined(__CUDA_ARCH_FEAT_SM100_ALL)
    extern __shared__ __align__(1024) unsigned char dsm[];
    __shared__ unsigned s_tmem;
    __shared__ __align__(8) unsigned long long s_full[2];
    __shared__ __align__(8) unsigned long long s_done[2];
    __shared__ float sbias[512];

    const unsigned smem_u = smem_u32(dsm);
    const int tid = threadIdx.x;
    const int wid = tid >> 5, lane = tid & 31;
    const int m0 = blockIdx.x * 128;

    sbias[tid] = bias[tid];
    sbias[tid + 256] = bias[tid + 256];

    if (tid == 0) {
        #pragma unroll
        for (int i = 0; i < 2; i++) {
            MBAR_INIT(smem_u32(&s_full[i]), 256);
            MBAR_INIT(smem_u32(&s_done[i]), 1);
        }
    }
    __syncthreads();
    if (wid == 0) TC_ALLOC(smem_u32(&s_tmem), 512);
    __syncthreads();
    const unsigned tmem = s_tmem;
    unsigned fullu[2] = { smem_u32(&s_full[0]), smem_u32(&s_full[1]) };
    unsigned doneu[2] = { smem_u32(&s_done[0]), smem_u32(&s_done[1]) };
    int mfp[2] = {0, 0}, dph[2] = {0, 0};

    const int ra = tid >> 1, ca = (tid & 1) * 4;
    const int ram = ra & 7;
    const __half* Asrc = A_g + (size_t)(m0 + ra) * Hdim;
    const int rb0 = tid, rb1 = tid + 256;
    const int rm0 = rb0 & 7, rm1 = rb1 & 7;
    const __half* Bs0 = B_g + (size_t)rb0 * Hdim;
    const __half* Bs1 = B_g + (size_t)rb1 * Hdim;

    #define LFILL(kc_, st_) do { \
        unsigned ab = smem_u + (st_) * STGL; \
        const __half* sh = Asrc + (kc_) * 64; \
        _Pragma("unroll") \
        for (int c = 0; c < 4; c++) { \
            int cc = ca + c; \
            unsigned d = ra * 128 + ((cc ^ ram) * 16); \
            CP16(ab + d, sh + cc * 8); \
        } \
        _Pragma("unroll") \
        for (int c = 0; c < 8; c++) { \
            unsigned d0 = rb0 * 128 + ((c ^ rm0) * 16); \
            unsigned d1 = rb1 * 128 + ((c ^ rm1) * 16); \
            CP16(ab + 16384 + d0, Bs0 + (kc_) * 64 + c * 8); \
            CP16(ab + 16384 + d1, Bs1 + (kc_) * 64 + c * 8); \
        } \
    } while (0)

    LFILL(0, 0); CP_ARRIVE(fullu[0]);
    LFILL(1, 1); CP_ARRIVE(fullu[1]);

    for (int kc = 0; kc < 16; kc++) {
        if (wid == 0 && elect1()) {
            int s = kc & 1;
            MBAR_WAIT(fullu[s], (unsigned)(mfp[s] & 1));
            mfp[s]++;
            unsigned sb = smem_u + s * STGL;
            unsigned long long ad = mk_desc(sb);
            #pragma unroll
            for (int nt = 0; nt < 8; nt++) {
                unsigned long long bd = mk_desc(sb + 16384 + nt * 8192);
                #pragma unroll
                for (int ks = 0; ks < 4; ks++) {
                    unsigned en0 = (kc == 0 && ks == 0) ? 0u : 1u;
                    tc_mma_f16_ss(tmem + nt * 64, ad + ks * 2, bd + ks * 2,
                                  IDESC_F16, en0);
                }
            }
            TC_COMMIT(doneu[s]);
        }
        if (kc + 2 < 16) {
            int s = kc & 1;
            MBAR_WAIT(doneu[s], (unsigned)(dph[s] & 1));
            dph[s]++;
            LFILL(kc + 2, s);
            CP_ARRIVE(fullu[s]);
        }
    }
    MBAR_WAIT(doneu[0], (unsigned)(dph[0] & 1)); dph[0]++;
    MBAR_WAIT(doneu[1], (unsigned)(dph[1] & 1)); dph[1]++;
    TC_FENCE_AFTER();

    // epilogue: 2 row-groups of 64, stage to S[64][517], softmax/NLL
    float* S = (float*)dsm;
    const int sub = wid & 3;
    const int chalf = wid >> 2;
    #pragma unroll
    for (int g = 0; g < 2; g++) {
        if ((sub >> 1) == g) {
            int lrow = (sub & 1) * 32 + lane;
            #pragma unroll
            for (int c = 0; c < 8; c++) {
                int col = chalf * 256 + c * 32;
                unsigned dr[32];
                TC_LD32(dr, tmem + col);
                TC_WAIT_LD();
                TC_FENCE_BEFORE();
                #pragma unroll
                for (int q = 0; q < 32; q++)
                    S[lrow * 517 + col + q] = __uint_as_float(dr[q]) + sbias[col + q];
            }
        }
        __syncthreads();
        {
            int row = tid >> 2, q = tid & 3;
            const float* Sr = S + row * 517 + q * 128;
            float mx = -1e30f;
            for (int i = 0; i < 128; i++) mx = fmaxf(mx, Sr[i]);
            mx = fmaxf(mx, __shfl_xor_sync(0xffffffffu, mx, 1));
            mx = fmaxf(mx, __shfl_xor_sync(0xffffffffu, mx, 2));
            float sm = 0.f;
            for (int i = 0; i < 128; i++) sm += __expf(Sr[i] - mx);
            sm += __shfl_xor_sync(0xffffffffu, sm, 1);
            sm += __shfl_xor_sync(0xffffffffu, sm, 2);
            if (q == 0) {
                int r = m0 + g * 64 + row;
                int t = r >> 8, b = r & 255;
                int tgt = atom_truth[b * Tlen + t];
                float lp = S[row * 517 + tgt] - mx - logf(sm);
                int mode = g_mask_mode;
                float m;
                if (mode == 2)      m = (((const float*)atom_mask)[b * Tlen + t] != 0.f) ? 1.f : 0.f;
                else if (mode == 1) m = (((const unsigned char*)atom_mask)[b * Tlen + t] != 0) ? 1.f : 0.f;
                else                m = (((const int*)atom_mask)[b * Tlen + t] != 0) ? 1.f : 0.f;
                rownll[r]  = -lp * m;
                rowmask[r] = m;
            }
        }
        __syncthreads();
    }
    if (wid == 0) TC_DEALLOC(tmem, 512);
    #undef LFILL
#endif
}

// ---------------------------------------------------------------------------
// Fallback logits (mma.sync) + fallback NLL — no-op when tcgen05 active.
// ---------------------------------------------------------------------------
__global__ __launch_bounds__(256) void logits_mma(
    const __half* __restrict__ A_g,
    const __half* __restrict__ B_g,
    float* __restrict__ C,
    const float* __restrict__ bias)
{
    if (g_use_tc) return;
    extern __shared__ __align__(16) unsigned char dsm2[];
    unsigned smem_u = (unsigned)__cvta_generic_to_shared(dsm2);

    const int n0 = blockIdx.x * 128;
    const int m0 = blockIdx.y * 64;
    const int tid = threadIdx.x;
    const int lane = tid & 31, w = tid >> 5;
    const int wm = w & 1, wn = w >> 1;
    const int qr = lane >> 2, qk = (lane & 3) * 2;
    const int ar = tid >> 2, akc = (tid & 3) * 8;
    const int br = tid >> 1, bkc = (tid & 1) * 16;

    float acc[2][4][4];
    #pragma unroll
    for (int mt = 0; mt < 2; mt++)
        #pragma unroll
        for (int nt = 0; nt < 4; nt++)
            #pragma unroll
            for (int q = 0; q < 4; q++) acc[mt][nt][q] = 0.f;

    mma_mainloop1(A_g + (size_t)(m0 + ar) * Hdim + akc,
                  B_g + (size_t)(n0 + br) * Hdim + bkc,
                  smem_u, tid, acc);

    #pragma unroll
    for (int mt = 0; mt < 2; mt++)
        #pragma unroll
        for (int nt = 0; nt < 4; nt++) {
            int m = m0 + wm * 32 + mt * 16 + qr;
            int n = n0 + wn * 32 + nt * 8 + qk;
            float b0v = bias[n], b1v = bias[n + 1];
            *(float2*)&C[(size_t)m * NTAG + n] =
                make_float2(acc[mt][nt][0] + b0v, acc[mt][nt][1] + b1v);
            *(float2*)&C[(size_t)(m + 8) * NTAG + n] =
                make_float2(acc[mt][nt][2] + b0v, acc[mt][nt][3] + b1v);
        }
}

__global__ __launch_bounds__(256) void nll_fallback(
    const float* __restrict__ logits,
    const int* __restrict__ atom_truth,
    const void* __restrict__ atom_mask,
    float* __restrict__ rownll,
    float* __restrict__ rowmask)
{
    if (g_use_tc) return;
    const int w = threadIdx.x >> 5, lane = threadIdx.x & 31;
    for (int i = 0; i < 16; i++) {
        int r = blockIdx.x * 128 + w * 16 + i;
        const float* row = logits + (size_t)r * NTAG;
        float mx = -1e30f;
        for (int c = lane; c < NTAG; c += 32) mx = fmaxf(mx, row[c]);
        #pragma unroll
        for (int s = 16; s; s >>= 1) mx = fmaxf(mx, __shfl_xor_sync(0xffffffffu, mx, s));
        float sm = 0.f;
        for (int c = lane; c < NTAG; c += 32) sm += __expf(row[c] - mx);
        #pragma unroll
        for (int s = 16; s; s >>= 1) sm += __shfl_xor_sync(0xffffffffu, sm, s);
        if (lane == 0) {
            int t = r >> 8, b = r & 255;
            int tgt = atom_truth[b * Tlen + t];
            float lp = row[tgt] - mx - logf(sm);
            int mode = g_mask_mode;
            float m;
            if (mode == 2)      m = (((const float*)atom_mask)[b * Tlen + t] != 0.f) ? 1.f : 0.f;
            else if (mode == 1) m = (((const unsigned char*)atom_mask)[b * Tlen + t] != 0) ? 1.f : 0.f;
            else                m = (((const int*)atom_mask)[b * Tlen + t] != 0) ? 1.f : 0.f;
            rownll[r]  = -lp * m;
            rowmask[r] = m;
        }
    }
}

// ---------------------------------------------------------------------------
// Mask detection / final reduction
// ---------------------------------------------------------------------------
__global__ void detect_mask(const unsigned* __restrict__ m)
{
    __shared__ int isByte, isFloat;
    if (threadIdx.x == 0) { isByte = 0; isFloat = 0; }
    __syncthreads();
    for (int i = threadIdx.x; i < (Bsz * Tlen) / 4; i += blockDim.x) {
        unsigned v = m[i];
        if (v == 0x3F800000u) isFloat = 1;
        else if (v > 1u) isByte = 1;
    }
    __syncthreads();
    if (threadIdx.x == 0) g_mask_mode = isFloat ? 2 : (isByte ? 1 : 0);
}

__global__ __launch_bounds__(256) void final_reduce(
    const float* __restrict__ rownll,
    const float* __restrict__ rowmask,
    float* __restrict__ out)
{
    __shared__ double rn[256], rm[256];
    double sn = 0.0, sm = 0.0;
    for (int i = threadIdx.x; i < Tlen * Bsz; i += 256) {
        sn += (double)rownll[i];
        sm += (double)rowmask[i];
    }
    rn[threadIdx.x] = sn; rm[threadIdx.x] = sm;
    __syncthreads();
    for (int s = 128; s > 0; s >>= 1) {
        if (threadIdx.x < s) {
            rn[threadIdx.x] += rn[threadIdx.x + s];
            rm[threadIdx.x] += rm[threadIdx.x + s];
        }
        __syncthreads();
    }
    if (threadIdx.x == 0) out[0] = (float)(rn[0] / rm[0]);
}

// ---------------------------------------------------------------------------
// Launch
// ---------------------------------------------------------------------------
extern "C" void kernel_launch(void* const* d_in, const int* in_sizes, int n_in,
                              void* d_out, int out_size)
{
    const float* x      = (const float*)d_in[0];
    const int*   atomtr = (const int*)d_in[1];
    const void*  mask   = d_in[2];
    const float* emb    = (const float*)d_in[3];
    const float* W_ih   = (const float*)d_in[4];
    const float* W_hh   = (const float*)d_in[5];
    const float* b_ih   = (const float*)d_in[6];
    const float* b_hh   = (const float*)d_in[7];
    const float* W_out  = (const float*)d_in[8];
    const float* b_out  = (const float*)d_in[9];
    const float* h0     = (const float*)d_in[10];
    const float* c0     = (const float*)d_in[11];

    float* sc = nullptr;
    cudaGetSymbolAddress((void**)&sc, g_scratch);
    float* xpart   = sc + 0;
    float* embproj = sc + 1048576;
    float* logits  = sc + 3407872;
    float* rownll  = sc + 11796480;
    float* rowmask = sc + 11812864;
    __half* hb = (__half*)(sc + 11829248);
    __half* whh  = hb + 0;
    __half* wout = hb + 8388608;
    __half* hA   = hb + 9437184;
    __half* hB   = hb + 9699328;
    __half* hs   = hb + 9961472;

    const int DSMEM_LOG = 3 * 15360;   // fallback logits: 46080
    static int attr_done = 0;
    if (!attr_done) {
        cudaFuncSetAttribute(lstm_seq,      cudaFuncAttributeMaxDynamicSharedMemorySize, DSMEM_LSTM);
        cudaFuncSetAttribute(logits_nll_tc, cudaFuncAttributeMaxDynamicSharedMemorySize, DSMEM_LOGTC);
        cudaFuncSetAttribute(logits_mma,    cudaFuncAttributeMaxDynamicSharedMemorySize, DSMEM_LOG);
        attr_done = 1;
    }

    detect_mask<<<1, 256>>>((const unsigned*)mask);
    init_bar<<<1, 1>>>();

    // one-time weight / state conversions (single fp16)
    interleave_whh<<<4096, 256>>>(W_hh, whh);
    conv16<<<512, 256>>>(W_out, wout);
    conv16<<<256, 256>>>(h0, hA);

    // merged projection: xpart + embproj in one launch (grid 64x6)
    proj_dual<<<dim3(G4 / 64, 6), 256>>>(x, emb, W_ih, xpart, embproj, b_ih, b_hh);

    // all 64 LSTM steps in one persistent kernel
    lstm_seq<<<128, 256, DSMEM_LSTM>>>(
        hA, hB, c0, xpart, embproj, hs, whh, atomtr);

    // fused logits + softmax + NLL (tcgen05; empty body on plain pass)
    logits_nll_tc<<<128, 256, DSMEM_LOGTC>>>(
        hs, wout, b_out, atomtr, mask, rownll, rowmask);

    // fallback path (no-ops when tcgen05 cubin active)
    logits_mma<<<dim3(NTAG / 128, (Tlen * Bsz) / 64), 256, DSMEM_LOG>>>(
        hs, wout, logits, b_out);
    nll_fallback<<<(Tlen * Bsz) / 128, 256>>>(logits, atomtr, mask, rownll, rowmask);

    final_reduce<<<1, 256>>>(rownll, rowmask, (float*)d_out);
}